// round 8
// baseline (speedup 1.0000x reference)
#include <cuda_runtime.h>
#include <cuda_bf16.h>
#include <stdint.h>
#include <math.h>

#define BATCH 8
#define CH    128
#define NPIX  4096
#define BR    128
#define BC    64
#define NT    (NPIX / BC)   // 64

// bf16 hi/lo split operands (emulated-fp32 MMA)
__device__ __align__(16) __nv_bfloat16 g_Qhi[BATCH * NPIX * CH];  // [b][n][c]
__device__ __align__(16) __nv_bfloat16 g_Qlo[BATCH * NPIX * CH];
__device__ __align__(16) __nv_bfloat16 g_Khi[BATCH * NPIX * CH];  // [b][n][c]
__device__ __align__(16) __nv_bfloat16 g_Klo[BATCH * NPIX * CH];
__device__ __align__(16) __nv_bfloat16 g_Vhi[BATCH * CH * NPIX];  // [b][c][n]
__device__ __align__(16) __nv_bfloat16 g_Vlo[BATCH * CH * NPIX];

typedef unsigned long long u64;

__device__ __forceinline__ uint32_t smem_u32(const void* p) {
    uint32_t a;
    asm("{ .reg .u64 t; cvta.to.shared.u64 t, %1; cvt.u32.u64 %0, t; }" : "=r"(a) : "l"(p));
    return a;
}
__device__ __forceinline__ void cpasync16(uint32_t dst, const void* src) {
    asm volatile("cp.async.cg.shared.global [%0], [%1], 16;" :: "r"(dst), "l"(src));
}
#define CP_COMMIT() asm volatile("cp.async.commit_group;" ::: "memory")
#define CP_WAIT0()  asm volatile("cp.async.wait_group 0;" ::: "memory")
#define CP_WAIT1()  asm volatile("cp.async.wait_group 1;" ::: "memory")

// ---- packed f32x2 helpers ----
__device__ __forceinline__ void fma2(u64& d, u64 a, u64 b) {
    asm("fma.rn.f32x2 %0, %1, %2, %0;" : "+l"(d) : "l"(a), "l"(b));
}
__device__ __forceinline__ u64 pack2(float lo, float hi) {
    u64 d; asm("mov.b64 %0, {%1, %2};" : "=l"(d) : "f"(lo), "f"(hi)); return d;
}
__device__ __forceinline__ float2 unpack2(u64 a) {
    float2 r; asm("mov.b64 {%0, %1}, %2;" : "=f"(r.x), "=f"(r.y) : "l"(a)); return r;
}
__device__ __forceinline__ float ex2(float x) {
    float y; asm("ex2.approx.ftz.f32 %0, %1;" : "=f"(y) : "f"(x)); return y;
}

// m16n8k16 row.col bf16 -> fp32, D==C in place
__device__ __forceinline__ void mma16816(float* c,
    uint32_t a0, uint32_t a1, uint32_t a2, uint32_t a3, uint32_t b0, uint32_t b1) {
    asm volatile(
        "mma.sync.aligned.m16n8k16.row.col.f32.bf16.bf16.f32 "
        "{%0,%1,%2,%3}, {%4,%5,%6,%7}, {%8,%9}, {%0,%1,%2,%3};"
        : "+f"(c[0]), "+f"(c[1]), "+f"(c[2]), "+f"(c[3])
        : "r"(a0), "r"(a1), "r"(a2), "r"(a3), "r"(b0), "r"(b1));
}

// ldmatrix x4 non-trans
__device__ __forceinline__ void ldsm4(uint32_t& r0, uint32_t& r1, uint32_t& r2,
                                      uint32_t& r3, uint32_t addr) {
    asm volatile("ldmatrix.sync.aligned.m8n8.x4.shared.b16 {%0,%1,%2,%3}, [%4];"
                 : "=r"(r0), "=r"(r1), "=r"(r2), "=r"(r3) : "r"(addr));
}

// pack (pe,po) fp32 pair -> bf16x2 hi + bf16x2 lo (pe in low half)
__device__ __forceinline__ void splitP(float pe, float po, uint32_t& h, uint32_t& l) {
    uint32_t hh;
    asm("cvt.rn.bf16x2.f32 %0, %1, %2;" : "=r"(hh) : "f"(po), "f"(pe));
    __nv_bfloat162 hb = *reinterpret_cast<__nv_bfloat162*>(&hh);
    float2 hf = __bfloat1622float2(hb);
    uint32_t ll;
    asm("cvt.rn.bf16x2.f32 %0, %1, %2;" : "=r"(ll) : "f"(po - hf.y), "f"(pe - hf.x));
    h = hh; l = ll;
}
__device__ __forceinline__ void split2(float a, float b, uint32_t& hi, uint32_t& lo) {
    __nv_bfloat162 h = __floats2bfloat162_rn(a, b);
    float2 hf = __bfloat1622float2(h);
    __nv_bfloat162 l = __floats2bfloat162_rn(a - hf.x, b - hf.y);
    union { __nv_bfloat162 v; uint32_t u; } ch, cl;
    ch.v = h; cl.v = l;
    hi = ch.u; lo = cl.u;
}

// ================= QKV projection -> bf16 hi/lo (f32x2 inner loop) =================
#define PROJ_SMEM_FLOATS (CH * 132 + CH * 128)
#define LOG2E 1.4426950408889634f

__global__ void __launch_bounds__(256, 1) qkv_kernel(
    const float* __restrict__ x1, const float* __restrict__ x2,
    const float* __restrict__ Wq, const float* __restrict__ bq,
    const float* __restrict__ Wk, const float* __restrict__ bk,
    const float* __restrict__ Wv, const float* __restrict__ bv)
{
    extern __shared__ __align__(16) float sm[];
    float* Wt = sm;
    float* Xs = sm + CH * 132;

    const int t = threadIdx.x, tx = t & 15, ty = t >> 4;
    const int which = blockIdx.y, b = blockIdx.z, p0 = blockIdx.x * 128;

    const float* X    = (which == 0 ? x1 : x2) + (size_t)b * CH * NPIX;
    const float* W    = (which == 0 ? Wq : (which == 1 ? Wk : Wv));
    const float* bias = (which == 0 ? bq : (which == 1 ? bk : bv));

#pragma unroll
    for (int it = 0; it < 8; ++it) {
        int oo = ty + 16 * it;
#pragma unroll
        for (int h = 0; h < 2; ++h) {
            int cc = 64 * h + 4 * tx;
            float4 w4 = *(const float4*)&W[oo * CH + cc];
            Wt[(cc + 0) * 132 + oo] = w4.x;
            Wt[(cc + 1) * 132 + oo] = w4.y;
            Wt[(cc + 2) * 132 + oo] = w4.z;
            Wt[(cc + 3) * 132 + oo] = w4.w;
        }
    }
#pragma unroll
    for (int it = 0; it < 8; ++it) {
        int cc = ty + 16 * it;
#pragma unroll
        for (int h = 0; h < 2; ++h) {
            int pp = 64 * h + 4 * tx;
            *(float4*)&Xs[cc * 128 + pp] = *(const float4*)&X[(size_t)cc * NPIX + p0 + pp];
        }
    }
    __syncthreads();

    u64 acc2[8][4];
#pragma unroll
    for (int i = 0; i < 8; ++i)
#pragma unroll
        for (int p = 0; p < 4; ++p) acc2[i][p] = 0ull;

#pragma unroll 4
    for (int c = 0; c < CH; ++c) {
        float4 wa = *(const float4*)&Wt[c * 132 + 4 * ty];
        float4 wb = *(const float4*)&Wt[c * 132 + 64 + 4 * ty];
        ulonglong2 xa = *(const ulonglong2*)&Xs[c * 128 + 4 * tx];
        ulonglong2 xb = *(const ulonglong2*)&Xs[c * 128 + 64 + 4 * tx];
        float wv[8] = {wa.x, wa.y, wa.z, wa.w, wb.x, wb.y, wb.z, wb.w};
#pragma unroll
        for (int i = 0; i < 8; ++i) {
            u64 w = pack2(wv[i], wv[i]);
            fma2(acc2[i][0], w, xa.x);
            fma2(acc2[i][1], w, xa.y);
            fma2(acc2[i][2], w, xb.x);
            fma2(acc2[i][3], w, xb.y);
        }
    }

    float acc[8][8];
#pragma unroll
    for (int i = 0; i < 8; ++i)
#pragma unroll
        for (int p = 0; p < 4; ++p) {
            float2 v = unpack2(acc2[i][p]);
            acc[i][2 * p] = v.x;
            acc[i][2 * p + 1] = v.y;
        }

    if (which < 2) {
        const float qsc = (which == 0) ? LOG2E : 1.0f;
        __syncthreads();
        float* T = sm;  // [p][132]
#pragma unroll
        for (int i = 0; i < 8; ++i) {
            int o = (i < 4) ? (4 * ty + i) : (64 + 4 * ty + i - 4);
            float bo = bias[o];
#pragma unroll
            for (int j = 0; j < 8; ++j) {
                int p = (j < 4) ? (4 * tx + j) : (64 + 4 * tx + j - 4);
                T[p * 132 + o] = (acc[i][j] + bo) * qsc;
            }
        }
        __syncthreads();
        __nv_bfloat16* dHi = (which == 0 ? g_Qhi : g_Khi);
        __nv_bfloat16* dLo = (which == 0 ? g_Qlo : g_Klo);
        int p = t >> 1, h = t & 1;
        const float* src = T + p * 132 + 64 * h;
        size_t base = ((size_t)b * NPIX + p0 + p) * CH + 64 * h;
        uint32_t hi[32], lo[32];
#pragma unroll
        for (int m = 0; m < 32; ++m)
            split2(src[2 * m], src[2 * m + 1], hi[m], lo[m]);
        uint4* dh = (uint4*)(dHi + base);
        uint4* dl = (uint4*)(dLo + base);
#pragma unroll
        for (int k = 0; k < 8; ++k) {
            dh[k] = make_uint4(hi[4 * k], hi[4 * k + 1], hi[4 * k + 2], hi[4 * k + 3]);
            dl[k] = make_uint4(lo[4 * k], lo[4 * k + 1], lo[4 * k + 2], lo[4 * k + 3]);
        }
    } else {
#pragma unroll
        for (int i = 0; i < 8; ++i) {
            int o = (i < 4) ? (4 * ty + i) : (64 + 4 * ty + i - 4);
            float bo = bias[o];
            size_t rb = ((size_t)b * CH + o) * NPIX + p0;
#pragma unroll
            for (int jg = 0; jg < 2; ++jg) {
                int p = 4 * tx + 64 * jg;
                uint32_t h0, l0, h1, l1;
                split2(acc[i][4 * jg] + bo, acc[i][4 * jg + 1] + bo, h0, l0);
                split2(acc[i][4 * jg + 2] + bo, acc[i][4 * jg + 3] + bo, h1, l1);
                *(uint2*)(g_Vhi + rb + p) = make_uint2(h0, h1);
                *(uint2*)(g_Vlo + rb + p) = make_uint2(l0, l1);
            }
        }
    }
}

// ==== flash attention: HMMA bf16x3, Q-frags in regs, triple buffer, deferred PV ====
// buffer i at i*71680; within buf: Khi +0, Klo +17408, Vhi +34816, Vlo +53248
#define BUFSZ 71680
#define ATTN_SMEM_BYTES (3 * BUFSZ)   // 215040

__global__ void __launch_bounds__(256, 1) attn_kernel(float* __restrict__ out)
{
    extern __shared__ __align__(16) uint32_t sm32[];
    const uint32_t sb = smem_u32(sm32);

    const int t = threadIdx.x;
    const int wid = t >> 5;
    const int lane = t & 31;
    const int l7 = lane & 7;
    const int r8 = lane >> 3;
    const int b = blockIdx.y;
    const int i0 = blockIdx.x * BR;

    const char* khg = (const char*)(g_Khi + (size_t)b * NPIX * CH);
    const char* klg = (const char*)(g_Klo + (size_t)b * NPIX * CH);
    const char* vhg = (const char*)(g_Vhi + (size_t)b * CH * NPIX);
    const char* vlg = (const char*)(g_Vlo + (size_t)b * CH * NPIX);

    // ---- stage Q hi/lo into buf2 area, then KV tile 0 into buf0 ----
    {
        const char* qh = (const char*)(g_Qhi + ((size_t)b * NPIX + i0) * CH);
        const char* ql = (const char*)(g_Qlo + ((size_t)b * NPIX + i0) * CH);
#pragma unroll
        for (int r = 0; r < 8; ++r) {
            int idx = t + 256 * r;            // 2048 x 16B per precision
            int row = idx >> 4, off = idx & 15;
            cpasync16(sb + 2 * BUFSZ + row * 272 + off * 16, qh + (size_t)idx * 16);
            cpasync16(sb + 2 * BUFSZ + 34816 + row * 272 + off * 16, ql + (size_t)idx * 16);
        }
        CP_COMMIT();
#pragma unroll
        for (int r = 0; r < 4; ++r) {
            int idx = t + 256 * r;
            int row = idx >> 4, off = idx & 15;
            cpasync16(sb + row * 272 + off * 16, khg + (size_t)idx * 16);
            cpasync16(sb + 17408 + row * 272 + off * 16, klg + (size_t)idx * 16);
        }
#pragma unroll
        for (int r = 0; r < 4; ++r) {
            int idx = t + 256 * r;
            int row = idx >> 3, off = idx & 7;
            cpasync16(sb + 34816 + row * 144 + off * 16, vhg + (size_t)row * NPIX * 2 + off * 16);
            cpasync16(sb + 53248 + row * 144 + off * 16, vlg + (size_t)row * NPIX * 2 + off * 16);
        }
        CP_COMMIT();
    }

    // ---- Q fragments -> registers (loop-invariant) ----
    uint32_t qh[8][4], ql[8][4];
    {
        CP_WAIT1();            // Q group done (KV0 may still be in flight)
        __syncthreads();
        const uint32_t aH = sb + 2 * BUFSZ
            + (uint32_t)(wid * 16 + l7 + (r8 & 1) * 8) * 272 + (uint32_t)((lane >> 4) & 1) * 16;
        const uint32_t aL = aH + 34816;
#pragma unroll
        for (int kk = 0; kk < 8; ++kk) {
            ldsm4(qh[kk][0], qh[kk][1], qh[kk][2], qh[kk][3], aH + kk * 32);
            ldsm4(ql[kk][0], ql[kk][1], ql[kk][2], ql[kk][3], aL + kk * 32);
        }
    }

    float o[16][4];
#pragma unroll
    for (int n = 0; n < 16; ++n)
#pragma unroll
        for (int r = 0; r < 4; ++r) o[n][r] = 0.f;
    float lsum0 = 0.f, lsum1 = 0.f;
    uint32_t pa[4][8];   // split-P fragments of previous tile

    // B-operand per-lane offsets (byte)
    const uint32_t bRow = (uint32_t)((r8 >> 1) * 8 + l7);
    const uint32_t bOffK = bRow * 272 + (uint32_t)(r8 & 1) * 16;
    const uint32_t bOffV = bRow * 144 + (uint32_t)(r8 & 1) * 16;

    uint32_t dB = 0;                       // buf(jt%3) byte base
    uint32_t pB = 2 * BUFSZ;               // buf((jt-1)%3)

    for (int jt = 0; jt < NT; ++jt) {
        CP_WAIT0();
        __syncthreads();   // K/V(jt) ready; all warps finished tile jt-1 (incl PV(jt-2))

        // prefetch tile jt+1 into buf (jt+1)%3
        const uint32_t nB = (dB == 2 * BUFSZ) ? 0u : dB + BUFSZ;
        if (jt + 1 < NT) {
            const int j0n = (jt + 1) * BC;
            const char* kh = khg + (size_t)j0n * CH * 2;
            const char* kl = klg + (size_t)j0n * CH * 2;
            const char* vh = vhg + (size_t)j0n * 2;
            const char* vl = vlg + (size_t)j0n * 2;
#pragma unroll
            for (int r = 0; r < 4; ++r) {
                int idx = t + 256 * r;
                int row = idx >> 4, off = idx & 15;
                cpasync16(sb + nB + row * 272 + off * 16, kh + (size_t)idx * 16);
                cpasync16(sb + nB + 17408 + row * 272 + off * 16, kl + (size_t)idx * 16);
            }
#pragma unroll
            for (int r = 0; r < 4; ++r) {
                int idx = t + 256 * r;
                int row = idx >> 3, off = idx & 7;
                cpasync16(sb + nB + 34816 + row * 144 + off * 16,
                          vh + (size_t)row * NPIX * 2 + off * 16);
                cpasync16(sb + nB + 53248 + row * 144 + off * 16,
                          vl + (size_t)row * NPIX * 2 + off * 16);
            }
        }
        CP_COMMIT();   // commit even when empty to keep group counting uniform

        // ---- S(jt) = Q K^T (Q frags from registers) ----
        float s[8][4];
#pragma unroll
        for (int n = 0; n < 8; ++n)
#pragma unroll
            for (int r = 0; r < 4; ++r) s[n][r] = 0.f;

        const uint32_t kBase = sb + dB + bOffK;
#pragma unroll
        for (int kk = 0; kk < 8; ++kk) {
#pragma unroll
            for (int np = 0; np < 4; ++np) {
                uint32_t b00, b01, b10, b11, c00, c01, c10, c11;
                ldsm4(b00, b01, b10, b11, kBase + np * 4352 + kk * 32);
                ldsm4(c00, c01, c10, c11, kBase + 17408 + np * 4352 + kk * 32);
                mma16816(s[2 * np],     qh[kk][0], qh[kk][1], qh[kk][2], qh[kk][3], b00, b01);
                mma16816(s[2 * np],     ql[kk][0], ql[kk][1], ql[kk][2], ql[kk][3], b00, b01);
                mma16816(s[2 * np],     qh[kk][0], qh[kk][1], qh[kk][2], qh[kk][3], c00, c01);
                mma16816(s[2 * np + 1], qh[kk][0], qh[kk][1], qh[kk][2], qh[kk][3], b10, b11);
                mma16816(s[2 * np + 1], ql[kk][0], ql[kk][1], ql[kk][2], ql[kk][3], b10, b11);
                mma16816(s[2 * np + 1], qh[kk][0], qh[kk][1], qh[kk][2], qh[kk][3], c10, c11);
            }
        }

        // ---- deferred PV(jt-1): reads buf (jt-1)%3, hides S drain + exp ----
        if (jt) {
            const uint32_t vBase = sb + pB + 34816 + bOffV;
#pragma unroll
            for (int kk = 0; kk < 4; ++kk) {
#pragma unroll
                for (int n2 = 0; n2 < 8; ++n2) {
                    uint32_t b00, b01, b10, b11, c00, c01, c10, c11;
                    ldsm4(b00, b01, b10, b11, vBase + n2 * 2304 + kk * 32);
                    ldsm4(c00, c01, c10, c11, vBase + 18432 + n2 * 2304 + kk * 32);
                    mma16816(o[2 * n2],     pa[kk][0], pa[kk][1], pa[kk][2], pa[kk][3], b00, b01);
                    mma16816(o[2 * n2],     pa[kk][4], pa[kk][5], pa[kk][6], pa[kk][7], b00, b01);
                    mma16816(o[2 * n2],     pa[kk][0], pa[kk][1], pa[kk][2], pa[kk][3], c00, c01);
                    mma16816(o[2 * n2 + 1], pa[kk][0], pa[kk][1], pa[kk][2], pa[kk][3], b10, b11);
                    mma16816(o[2 * n2 + 1], pa[kk][4], pa[kk][5], pa[kk][6], pa[kk][7], b10, b11);
                    mma16816(o[2 * n2 + 1], pa[kk][0], pa[kk][1], pa[kk][2], pa[kk][3], c10, c11);
                }
            }
        }

        // ---- exp2 (no max; log2e folded into Q) + partial row sums ----
#pragma unroll
        for (int n = 0; n < 8; ++n) {
            s[n][0] = ex2(s[n][0]);
            s[n][1] = ex2(s[n][1]);
            s[n][2] = ex2(s[n][2]);
            s[n][3] = ex2(s[n][3]);
            lsum0 += s[n][0] + s[n][1];
            lsum1 += s[n][2] + s[n][3];
        }

        // ---- split P(jt) -> pa (consumed by PV at jt+1) ----
#pragma unroll
        for (int kk = 0; kk < 4; ++kk) {
            splitP(s[2 * kk][0],     s[2 * kk][1],     pa[kk][0], pa[kk][4]);
            splitP(s[2 * kk][2],     s[2 * kk][3],     pa[kk][1], pa[kk][5]);
            splitP(s[2 * kk + 1][0], s[2 * kk + 1][1], pa[kk][2], pa[kk][6]);
            splitP(s[2 * kk + 1][2], s[2 * kk + 1][3], pa[kk][3], pa[kk][7]);
        }

        pB = dB;
        dB = nB;
    }

    // ---- final PV(NT-1) ----
    {
        const uint32_t vBase = sb + pB + 34816 + bOffV;
#pragma unroll
        for (int kk = 0; kk < 4; ++kk) {
#pragma unroll
            for (int n2 = 0; n2 < 8; ++n2) {
                uint32_t b00, b01, b10, b11, c00, c01, c10, c11;
                ldsm4(b00, b01, b10, b11, vBase + n2 * 2304 + kk * 32);
                ldsm4(c00, c01, c10, c11, vBase + 18432 + n2 * 2304 + kk * 32);
                mma16816(o[2 * n2],     pa[kk][0], pa[kk][1], pa[kk][2], pa[kk][3], b00, b01);
                mma16816(o[2 * n2],     pa[kk][4], pa[kk][5], pa[kk][6], pa[kk][7], b00, b01);
                mma16816(o[2 * n2],     pa[kk][0], pa[kk][1], pa[kk][2], pa[kk][3], c00, c01);
                mma16816(o[2 * n2 + 1], pa[kk][0], pa[kk][1], pa[kk][2], pa[kk][3], b10, b11);
                mma16816(o[2 * n2 + 1], pa[kk][4], pa[kk][5], pa[kk][6], pa[kk][7], b10, b11);
                mma16816(o[2 * n2 + 1], pa[kk][0], pa[kk][1], pa[kk][2], pa[kk][3], c10, c11);
            }
        }
    }

    // ---- epilogue: normalize, transpose via smem, coalesced store ----
    lsum0 += __shfl_xor_sync(0xffffffffu, lsum0, 1);
    lsum0 += __shfl_xor_sync(0xffffffffu, lsum0, 2);
    lsum1 += __shfl_xor_sync(0xffffffffu, lsum1, 1);
    lsum1 += __shfl_xor_sync(0xffffffffu, lsum1, 2);
    const float inv0 = 1.f / lsum0, inv1 = 1.f / lsum1;

    __syncthreads();
    float* Os = (float*)sm32;  // [c:128][i:132]
    {
        const int g = lane >> 2, q = lane & 3;
        const int i = wid * 16 + g;
#pragma unroll
        for (int n = 0; n < 16; ++n) {
            const int c = n * 8 + 2 * q;
            Os[(c    ) * 132 + i]     = o[n][0] * inv0;
            Os[(c + 1) * 132 + i]     = o[n][1] * inv0;
            Os[(c    ) * 132 + i + 8] = o[n][2] * inv1;
            Os[(c + 1) * 132 + i + 8] = o[n][3] * inv1;
        }
    }
    __syncthreads();
    {
        const int c = t >> 1, h = t & 1;
        const float* src = Os + c * 132 + 64 * h;
        float* dst = out + ((size_t)b * CH + c) * NPIX + i0 + 64 * h;
#pragma unroll
        for (int k = 0; k < 16; ++k)
            ((float4*)dst)[k] = make_float4(src[4 * k], src[4 * k + 1],
                                            src[4 * k + 2], src[4 * k + 3]);
    }
}

// ============================================================
extern "C" void kernel_launch(void* const* d_in, const int* in_sizes, int n_in,
                              void* d_out, int out_size)
{
    (void)in_sizes; (void)n_in; (void)out_size;
    const float* x1 = (const float*)d_in[0];
    const float* x2 = (const float*)d_in[1];
    const float* Wq = (const float*)d_in[2];
    const float* bq = (const float*)d_in[3];
    const float* Wk = (const float*)d_in[4];
    const float* bk = (const float*)d_in[5];
    const float* Wv = (const float*)d_in[6];
    const float* bv = (const float*)d_in[7];
    float* out = (float*)d_out;

    const int proj_smem = PROJ_SMEM_FLOATS * (int)sizeof(float);
    cudaFuncSetAttribute(qkv_kernel, cudaFuncAttributeMaxDynamicSharedMemorySize, proj_smem);
    cudaFuncSetAttribute(attn_kernel, cudaFuncAttributeMaxDynamicSharedMemorySize, ATTN_SMEM_BYTES);

    qkv_kernel<<<dim3(NPIX / 128, 3, BATCH), 256, proj_smem>>>(x1, x2, Wq, bq, Wk, bk, Wv, bv);
    attn_kernel<<<dim3(NPIX / BR, BATCH), 256, ATTN_SMEM_BYTES>>>(out);
}

// round 9
// speedup vs baseline: 1.0664x; 1.0664x over previous
#include <cuda_runtime.h>
#include <cuda_bf16.h>
#include <stdint.h>
#include <math.h>

#define BATCH 8
#define CH    128
#define NPIX  4096
#define BR    128
#define BC    64
#define NT    (NPIX / BC)   // 64
#define JSPLIT 4
#define TILES_PER_UNIT (NT / JSPLIT)   // 16

// bf16 hi/lo split operands (emulated-fp32 MMA)
__device__ __align__(16) __nv_bfloat16 g_Qhi[BATCH * NPIX * CH];  // [b][n][c]
__device__ __align__(16) __nv_bfloat16 g_Qlo[BATCH * NPIX * CH];
__device__ __align__(16) __nv_bfloat16 g_Khi[BATCH * NPIX * CH];  // [b][n][c]
__device__ __align__(16) __nv_bfloat16 g_Klo[BATCH * NPIX * CH];
__device__ __align__(16) __nv_bfloat16 g_Vhi[BATCH * CH * NPIX];  // [b][c][n]
__device__ __align__(16) __nv_bfloat16 g_Vlo[BATCH * CH * NPIX];

// split-j partial outputs: [b][jc][iblk][i 128][c 128], and row sums
__device__ __align__(16) float g_O[BATCH * JSPLIT * 32 * 128 * 128];  // 64 MB
__device__ __align__(16) float g_L[BATCH * JSPLIT * 32 * 128];

typedef unsigned long long u64;

__device__ __forceinline__ uint32_t smem_u32(const void* p) {
    uint32_t a;
    asm("{ .reg .u64 t; cvta.to.shared.u64 t, %1; cvt.u32.u64 %0, t; }" : "=r"(a) : "l"(p));
    return a;
}
__device__ __forceinline__ void cpasync16(uint32_t dst, const void* src) {
    asm volatile("cp.async.cg.shared.global [%0], [%1], 16;" :: "r"(dst), "l"(src));
}
#define CP_COMMIT() asm volatile("cp.async.commit_group;" ::: "memory")
#define CP_WAIT0()  asm volatile("cp.async.wait_group 0;" ::: "memory")

// ---- packed f32x2 helpers ----
__device__ __forceinline__ void fma2(u64& d, u64 a, u64 b) {
    asm("fma.rn.f32x2 %0, %1, %2, %0;" : "+l"(d) : "l"(a), "l"(b));
}
__device__ __forceinline__ u64 pack2(float lo, float hi) {
    u64 d; asm("mov.b64 %0, {%1, %2};" : "=l"(d) : "f"(lo), "f"(hi)); return d;
}
__device__ __forceinline__ float2 unpack2(u64 a) {
    float2 r; asm("mov.b64 {%0, %1}, %2;" : "=f"(r.x), "=f"(r.y) : "l"(a)); return r;
}
__device__ __forceinline__ float ex2(float x) {
    float y; asm("ex2.approx.ftz.f32 %0, %1;" : "=f"(y) : "f"(x)); return y;
}

// m16n8k16 row.col bf16 -> fp32, D==C in place
__device__ __forceinline__ void mma16816(float* c,
    uint32_t a0, uint32_t a1, uint32_t a2, uint32_t a3, uint32_t b0, uint32_t b1) {
    asm volatile(
        "mma.sync.aligned.m16n8k16.row.col.f32.bf16.bf16.f32 "
        "{%0,%1,%2,%3}, {%4,%5,%6,%7}, {%8,%9}, {%0,%1,%2,%3};"
        : "+f"(c[0]), "+f"(c[1]), "+f"(c[2]), "+f"(c[3])
        : "r"(a0), "r"(a1), "r"(a2), "r"(a3), "r"(b0), "r"(b1));
}

// ldmatrix x4 non-trans
__device__ __forceinline__ void ldsm4(uint32_t& r0, uint32_t& r1, uint32_t& r2,
                                      uint32_t& r3, uint32_t addr) {
    asm volatile("ldmatrix.sync.aligned.m8n8.x4.shared.b16 {%0,%1,%2,%3}, [%4];"
                 : "=r"(r0), "=r"(r1), "=r"(r2), "=r"(r3) : "r"(addr));
}

// pack (pe,po) fp32 pair -> bf16x2 hi + bf16x2 lo (pe in low half)
__device__ __forceinline__ void splitP(float pe, float po, uint32_t& h, uint32_t& l) {
    uint32_t hh;
    asm("cvt.rn.bf16x2.f32 %0, %1, %2;" : "=r"(hh) : "f"(po), "f"(pe));
    __nv_bfloat162 hb = *reinterpret_cast<__nv_bfloat162*>(&hh);
    float2 hf = __bfloat1622float2(hb);
    uint32_t ll;
    asm("cvt.rn.bf16x2.f32 %0, %1, %2;" : "=r"(ll) : "f"(po - hf.y), "f"(pe - hf.x));
    h = hh; l = ll;
}
__device__ __forceinline__ void split2(float a, float b, uint32_t& hi, uint32_t& lo) {
    __nv_bfloat162 h = __floats2bfloat162_rn(a, b);
    float2 hf = __bfloat1622float2(h);
    __nv_bfloat162 l = __floats2bfloat162_rn(a - hf.x, b - hf.y);
    union { __nv_bfloat162 v; uint32_t u; } ch, cl;
    ch.v = h; cl.v = l;
    hi = ch.u; lo = cl.u;
}

// ================= QKV projection -> bf16 hi/lo (f32x2 inner loop) =================
#define PROJ_SMEM_FLOATS (CH * 132 + CH * 128)
#define LOG2E 1.4426950408889634f

__global__ void __launch_bounds__(256, 1) qkv_kernel(
    const float* __restrict__ x1, const float* __restrict__ x2,
    const float* __restrict__ Wq, const float* __restrict__ bq,
    const float* __restrict__ Wk, const float* __restrict__ bk,
    const float* __restrict__ Wv, const float* __restrict__ bv)
{
    extern __shared__ __align__(16) float sm[];
    float* Wt = sm;
    float* Xs = sm + CH * 132;

    const int t = threadIdx.x, tx = t & 15, ty = t >> 4;
    const int which = blockIdx.y, b = blockIdx.z, p0 = blockIdx.x * 128;

    const float* X    = (which == 0 ? x1 : x2) + (size_t)b * CH * NPIX;
    const float* W    = (which == 0 ? Wq : (which == 1 ? Wk : Wv));
    const float* bias = (which == 0 ? bq : (which == 1 ? bk : bv));

#pragma unroll
    for (int it = 0; it < 8; ++it) {
        int oo = ty + 16 * it;
#pragma unroll
        for (int h = 0; h < 2; ++h) {
            int cc = 64 * h + 4 * tx;
            float4 w4 = *(const float4*)&W[oo * CH + cc];
            Wt[(cc + 0) * 132 + oo] = w4.x;
            Wt[(cc + 1) * 132 + oo] = w4.y;
            Wt[(cc + 2) * 132 + oo] = w4.z;
            Wt[(cc + 3) * 132 + oo] = w4.w;
        }
    }
#pragma unroll
    for (int it = 0; it < 8; ++it) {
        int cc = ty + 16 * it;
#pragma unroll
        for (int h = 0; h < 2; ++h) {
            int pp = 64 * h + 4 * tx;
            *(float4*)&Xs[cc * 128 + pp] = *(const float4*)&X[(size_t)cc * NPIX + p0 + pp];
        }
    }
    __syncthreads();

    u64 acc2[8][4];
#pragma unroll
    for (int i = 0; i < 8; ++i)
#pragma unroll
        for (int p = 0; p < 4; ++p) acc2[i][p] = 0ull;

#pragma unroll 4
    for (int c = 0; c < CH; ++c) {
        float4 wa = *(const float4*)&Wt[c * 132 + 4 * ty];
        float4 wb = *(const float4*)&Wt[c * 132 + 64 + 4 * ty];
        ulonglong2 xa = *(const ulonglong2*)&Xs[c * 128 + 4 * tx];
        ulonglong2 xb = *(const ulonglong2*)&Xs[c * 128 + 64 + 4 * tx];
        float wv[8] = {wa.x, wa.y, wa.z, wa.w, wb.x, wb.y, wb.z, wb.w};
#pragma unroll
        for (int i = 0; i < 8; ++i) {
            u64 w = pack2(wv[i], wv[i]);
            fma2(acc2[i][0], w, xa.x);
            fma2(acc2[i][1], w, xa.y);
            fma2(acc2[i][2], w, xb.x);
            fma2(acc2[i][3], w, xb.y);
        }
    }

    float acc[8][8];
#pragma unroll
    for (int i = 0; i < 8; ++i)
#pragma unroll
        for (int p = 0; p < 4; ++p) {
            float2 v = unpack2(acc2[i][p]);
            acc[i][2 * p] = v.x;
            acc[i][2 * p + 1] = v.y;
        }

    if (which < 2) {
        const float qsc = (which == 0) ? LOG2E : 1.0f;
        __syncthreads();
        float* T = sm;  // [p][132]
#pragma unroll
        for (int i = 0; i < 8; ++i) {
            int o = (i < 4) ? (4 * ty + i) : (64 + 4 * ty + i - 4);
            float bo = bias[o];
#pragma unroll
            for (int j = 0; j < 8; ++j) {
                int p = (j < 4) ? (4 * tx + j) : (64 + 4 * tx + j - 4);
                T[p * 132 + o] = (acc[i][j] + bo) * qsc;
            }
        }
        __syncthreads();
        __nv_bfloat16* dHi = (which == 0 ? g_Qhi : g_Khi);
        __nv_bfloat16* dLo = (which == 0 ? g_Qlo : g_Klo);
        int p = t >> 1, h = t & 1;
        const float* src = T + p * 132 + 64 * h;
        size_t base = ((size_t)b * NPIX + p0 + p) * CH + 64 * h;
        uint32_t hi[32], lo[32];
#pragma unroll
        for (int m = 0; m < 32; ++m)
            split2(src[2 * m], src[2 * m + 1], hi[m], lo[m]);
        uint4* dh = (uint4*)(dHi + base);
        uint4* dl = (uint4*)(dLo + base);
#pragma unroll
        for (int k = 0; k < 8; ++k) {
            dh[k] = make_uint4(hi[4 * k], hi[4 * k + 1], hi[4 * k + 2], hi[4 * k + 3]);
            dl[k] = make_uint4(lo[4 * k], lo[4 * k + 1], lo[4 * k + 2], lo[4 * k + 3]);
        }
    } else {
#pragma unroll
        for (int i = 0; i < 8; ++i) {
            int o = (i < 4) ? (4 * ty + i) : (64 + 4 * ty + i - 4);
            float bo = bias[o];
            size_t rb = ((size_t)b * CH + o) * NPIX + p0;
#pragma unroll
            for (int jg = 0; jg < 2; ++jg) {
                int p = 4 * tx + 64 * jg;
                uint32_t h0, l0, h1, l1;
                split2(acc[i][4 * jg] + bo, acc[i][4 * jg + 1] + bo, h0, l0);
                split2(acc[i][4 * jg + 2] + bo, acc[i][4 * jg + 3] + bo, h1, l1);
                *(uint2*)(g_Vhi + rb + p) = make_uint2(h0, h1);
                *(uint2*)(g_Vlo + rb + p) = make_uint2(l0, l1);
            }
        }
    }
}

// ==== flash attention partial: HMMA bf16x3, ldmatrix, split-j (16 tiles/unit) ====
#define QHI_B 0
#define QLO_B 34816
#define BUF_B 69632
#define BUFSTRIDE 71680
#define KHI_B(d) (BUF_B + (d) * BUFSTRIDE)
#define VHI_B(d) (KHI_B(d) + 2 * 17408)
#define ATTN_SMEM_BYTES (BUF_B + 2 * BUFSTRIDE)   // 212992

__global__ void __launch_bounds__(256, 1) attn_kernel()
{
    extern __shared__ __align__(16) uint32_t sm32[];
    const uint32_t sb = smem_u32(sm32);

    const int t = threadIdx.x;
    const int wid = t >> 5;
    const int lane = t & 31;
    const int l7 = lane & 7;
    const int r8 = lane >> 3;
    const int iblk = blockIdx.x;
    const int jc   = blockIdx.y;
    const int b    = blockIdx.z;
    const int i0 = iblk * BR;
    const int jt0 = jc * TILES_PER_UNIT;

    // ---- stage Q hi/lo (persistent) + prefetch first tile via cp.async ----
    {
        const char* qh = (const char*)(g_Qhi + ((size_t)b * NPIX + i0) * CH);
        const char* ql = (const char*)(g_Qlo + ((size_t)b * NPIX + i0) * CH);
#pragma unroll
        for (int r = 0; r < 8; ++r) {
            int idx = t + 256 * r;
            int row = idx >> 4, off = idx & 15;
            cpasync16(sb + QHI_B + row * 272 + off * 16, qh + (size_t)idx * 16);
            cpasync16(sb + QLO_B + row * 272 + off * 16, ql + (size_t)idx * 16);
        }
        const int j0 = jt0 * BC;
        const char* kh = (const char*)(g_Khi + ((size_t)b * NPIX + j0) * CH);
        const char* kl = (const char*)(g_Klo + ((size_t)b * NPIX + j0) * CH);
        const char* vh = (const char*)(g_Vhi + (size_t)b * CH * NPIX + j0);
        const char* vl = (const char*)(g_Vlo + (size_t)b * CH * NPIX + j0);
#pragma unroll
        for (int r = 0; r < 4; ++r) {
            int idx = t + 256 * r;
            int row = idx >> 4, off = idx & 15;
            cpasync16(sb + KHI_B(0) + row * 272 + off * 16, kh + (size_t)idx * 16);
            cpasync16(sb + KHI_B(0) + 17408 + row * 272 + off * 16, kl + (size_t)idx * 16);
        }
#pragma unroll
        for (int r = 0; r < 4; ++r) {
            int idx = t + 256 * r;
            int row = idx >> 3, off = idx & 7;
            cpasync16(sb + VHI_B(0) + row * 144 + off * 16,
                      vh + (size_t)row * NPIX * 2 + off * 16);
            cpasync16(sb + VHI_B(0) + 18432 + row * 144 + off * 16,
                      vl + (size_t)row * NPIX * 2 + off * 16);
        }
        CP_COMMIT();
    }

    float o[16][4];
#pragma unroll
    for (int n = 0; n < 16; ++n)
#pragma unroll
        for (int r = 0; r < 4; ++r) o[n][r] = 0.f;
    float lsum0 = 0.f, lsum1 = 0.f;

    // ldmatrix per-lane addresses
    const uint32_t aOffH = sb + QHI_B
        + (uint32_t)(wid * 16 + l7 + (r8 & 1) * 8) * 272 + (uint32_t)((lane >> 4) & 1) * 16;
    const uint32_t aOffL = aOffH + (QLO_B - QHI_B);
    const uint32_t bRow = (uint32_t)((r8 >> 1) * 8 + l7);
    const uint32_t bOffK = bRow * 272 + (uint32_t)(r8 & 1) * 16;
    const uint32_t bOffV = bRow * 144 + (uint32_t)(r8 & 1) * 16;

    for (int jt = jt0; jt < jt0 + TILES_PER_UNIT; ++jt) {
        const int d = jt & 1;
        CP_WAIT0();
        __syncthreads();   // tile d ready; all warps past previous compute

        // prefetch next tile into other buffer (overlaps with this tile's compute)
        if (jt + 1 < jt0 + TILES_PER_UNIT) {
            const int j0n = (jt + 1) * BC, dn = (jt + 1) & 1;
            const char* kh = (const char*)(g_Khi + ((size_t)b * NPIX + j0n) * CH);
            const char* kl = (const char*)(g_Klo + ((size_t)b * NPIX + j0n) * CH);
            const char* vh = (const char*)(g_Vhi + (size_t)b * CH * NPIX + j0n);
            const char* vl = (const char*)(g_Vlo + (size_t)b * CH * NPIX + j0n);
#pragma unroll
            for (int r = 0; r < 4; ++r) {
                int idx = t + 256 * r;
                int row = idx >> 4, off = idx & 15;
                cpasync16(sb + KHI_B(dn) + row * 272 + off * 16, kh + (size_t)idx * 16);
                cpasync16(sb + KHI_B(dn) + 17408 + row * 272 + off * 16, kl + (size_t)idx * 16);
            }
#pragma unroll
            for (int r = 0; r < 4; ++r) {
                int idx = t + 256 * r;
                int row = idx >> 3, off = idx & 7;
                cpasync16(sb + VHI_B(dn) + row * 144 + off * 16,
                          vh + (size_t)row * NPIX * 2 + off * 16);
                cpasync16(sb + VHI_B(dn) + 18432 + row * 144 + off * 16,
                          vl + (size_t)row * NPIX * 2 + off * 16);
            }
            CP_COMMIT();
        }

        // ---- S = Q K^T (3-term bf16 emulated fp32), ldmatrix loads ----
        float s[8][4];
#pragma unroll
        for (int n = 0; n < 8; ++n)
#pragma unroll
            for (int r = 0; r < 4; ++r) s[n][r] = 0.f;

        const uint32_t kBase = sb + KHI_B(d) + bOffK;
#pragma unroll
        for (int kk = 0; kk < 8; ++kk) {
            uint32_t a0h, a1h, a2h, a3h, a0l, a1l, a2l, a3l;
            ldsm4(a0h, a1h, a2h, a3h, aOffH + kk * 32);
            ldsm4(a0l, a1l, a2l, a3l, aOffL + kk * 32);
#pragma unroll
            for (int np = 0; np < 4; ++np) {
                uint32_t b00, b01, b10, b11, c00, c01, c10, c11;
                ldsm4(b00, b01, b10, b11, kBase + np * 4352 + kk * 32);
                ldsm4(c00, c01, c10, c11, kBase + 17408 + np * 4352 + kk * 32);
                mma16816(s[2 * np],     a0h, a1h, a2h, a3h, b00, b01);
                mma16816(s[2 * np],     a0l, a1l, a2l, a3l, b00, b01);
                mma16816(s[2 * np],     a0h, a1h, a2h, a3h, c00, c01);
                mma16816(s[2 * np + 1], a0h, a1h, a2h, a3h, b10, b11);
                mma16816(s[2 * np + 1], a0l, a1l, a2l, a3l, b10, b11);
                mma16816(s[2 * np + 1], a0h, a1h, a2h, a3h, c10, c11);
            }
        }

        // ---- exp2 (no max; log2e folded into Q) + partial row sums ----
#pragma unroll
        for (int n = 0; n < 8; ++n) {
            s[n][0] = ex2(s[n][0]);
            s[n][1] = ex2(s[n][1]);
            s[n][2] = ex2(s[n][2]);
            s[n][3] = ex2(s[n][3]);
            lsum0 += s[n][0] + s[n][1];
            lsum1 += s[n][2] + s[n][3];
        }

        // ---- O += P V (3-term); P split in registers ----
        const uint32_t vBase = sb + VHI_B(d) + bOffV;
#pragma unroll
        for (int kk = 0; kk < 4; ++kk) {
            uint32_t pa0h, pa0l, pa1h, pa1l, pa2h, pa2l, pa3h, pa3l;
            splitP(s[2 * kk][0],     s[2 * kk][1],     pa0h, pa0l);
            splitP(s[2 * kk][2],     s[2 * kk][3],     pa1h, pa1l);
            splitP(s[2 * kk + 1][0], s[2 * kk + 1][1], pa2h, pa2l);
            splitP(s[2 * kk + 1][2], s[2 * kk + 1][3], pa3h, pa3l);
#pragma unroll
            for (int n2 = 0; n2 < 8; ++n2) {
                uint32_t b00, b01, b10, b11, c00, c01, c10, c11;
                ldsm4(b00, b01, b10, b11, vBase + n2 * 2304 + kk * 32);
                ldsm4(c00, c01, c10, c11, vBase + 18432 + n2 * 2304 + kk * 32);
                mma16816(o[2 * n2],     pa0h, pa1h, pa2h, pa3h, b00, b01);
                mma16816(o[2 * n2],     pa0l, pa1l, pa2l, pa3l, b00, b01);
                mma16816(o[2 * n2],     pa0h, pa1h, pa2h, pa3h, c00, c01);
                mma16816(o[2 * n2 + 1], pa0h, pa1h, pa2h, pa3h, b10, b11);
                mma16816(o[2 * n2 + 1], pa0l, pa1l, pa2l, pa3l, b10, b11);
                mma16816(o[2 * n2 + 1], pa0h, pa1h, pa2h, pa3h, c10, c11);
            }
        }
        __syncthreads();   // done reading tile d before it is overwritten
    }

    // ---- epilogue: store raw partial O and L (merge kernel normalizes) ----
    lsum0 += __shfl_xor_sync(0xffffffffu, lsum0, 1);
    lsum0 += __shfl_xor_sync(0xffffffffu, lsum0, 2);
    lsum1 += __shfl_xor_sync(0xffffffffu, lsum1, 1);
    lsum1 += __shfl_xor_sync(0xffffffffu, lsum1, 2);

    const size_t unit = ((size_t)(b * JSPLIT + jc) * 32 + iblk);
    float* Ob = g_O + unit * (128 * 128);
    float* Lb = g_L + unit * 128;
    const int g = lane >> 2, q = lane & 3;
    const int i = wid * 16 + g;
    if ((lane & 3) == 0) {
        Lb[i]     = lsum0;
        Lb[i + 8] = lsum1;
    }
#pragma unroll
    for (int n = 0; n < 16; ++n) {
        const int c = n * 8 + 2 * q;
        *(float2*)&Ob[(size_t)i * 128 + c]       = make_float2(o[n][0], o[n][1]);
        *(float2*)&Ob[(size_t)(i + 8) * 128 + c] = make_float2(o[n][2], o[n][3]);
    }
}

// ==== merge kernel: sum 4 j-chunk partials, normalize, transpose, store ====
#define MERGE_SMEM_BYTES (128 * 129 * 4 + 128 * 4)   // 66560

__global__ void __launch_bounds__(256, 1) merge_kernel(float* __restrict__ out)
{
    extern __shared__ __align__(16) float ms[];
    float* Os   = ms;               // [c:128][i:129]
    float* Linv = ms + 128 * 129;

    const int t = threadIdx.x;
    const int iblk = blockIdx.x;
    const int b    = blockIdx.y;

    const float* O0 = g_O + ((size_t)(b * JSPLIT) * 32 + iblk) * (128 * 128);
    const size_t sj = (size_t)32 * 128 * 128;

    if (t < 128) {
        const float* L0 = g_L + ((size_t)(b * JSPLIT) * 32 + iblk) * 128 + t;
        const size_t lj = (size_t)32 * 128;
        float L = L0[0] + L0[lj] + L0[2 * lj] + L0[3 * lj];
        Linv[t] = 1.f / L;
    }

#pragma unroll
    for (int r = 0; r < 16; ++r) {
        int idx = (r * 256 + t) * 4;
        int i = idx >> 7, c = idx & 127;
        float4 a  = *(const float4*)&O0[idx];
        float4 b2 = *(const float4*)&O0[sj + idx];
        float4 c4 = *(const float4*)&O0[2 * sj + idx];
        float4 d4 = *(const float4*)&O0[3 * sj + idx];
        Os[(c + 0) * 129 + i] = a.x + b2.x + c4.x + d4.x;
        Os[(c + 1) * 129 + i] = a.y + b2.y + c4.y + d4.y;
        Os[(c + 2) * 129 + i] = a.z + b2.z + c4.z + d4.z;
        Os[(c + 3) * 129 + i] = a.w + b2.w + c4.w + d4.w;
    }
    __syncthreads();

    const int c = t >> 1, h = t & 1;
    const float* src = Os + c * 129 + 64 * h;
    const float* li  = Linv + 64 * h;
    float* dst = out + ((size_t)b * CH + c) * NPIX + iblk * 128 + 64 * h;
#pragma unroll
    for (int k = 0; k < 16; ++k) {
        ((float4*)dst)[k] = make_float4(src[4 * k]     * li[4 * k],
                                        src[4 * k + 1] * li[4 * k + 1],
                                        src[4 * k + 2] * li[4 * k + 2],
                                        src[4 * k + 3] * li[4 * k + 3]);
    }
}

// ============================================================
extern "C" void kernel_launch(void* const* d_in, const int* in_sizes, int n_in,
                              void* d_out, int out_size)
{
    (void)in_sizes; (void)n_in; (void)out_size;
    const float* x1 = (const float*)d_in[0];
    const float* x2 = (const float*)d_in[1];
    const float* Wq = (const float*)d_in[2];
    const float* bq = (const float*)d_in[3];
    const float* Wk = (const float*)d_in[4];
    const float* bk = (const float*)d_in[5];
    const float* Wv = (const float*)d_in[6];
    const float* bv = (const float*)d_in[7];
    float* out = (float*)d_out;

    const int proj_smem = PROJ_SMEM_FLOATS * (int)sizeof(float);
    cudaFuncSetAttribute(qkv_kernel, cudaFuncAttributeMaxDynamicSharedMemorySize, proj_smem);
    cudaFuncSetAttribute(attn_kernel, cudaFuncAttributeMaxDynamicSharedMemorySize, ATTN_SMEM_BYTES);
    cudaFuncSetAttribute(merge_kernel, cudaFuncAttributeMaxDynamicSharedMemorySize, MERGE_SMEM_BYTES);

    qkv_kernel<<<dim3(NPIX / 128, 3, BATCH), 256, proj_smem>>>(x1, x2, Wq, bq, Wk, bk, Wv, bv);
    attn_kernel<<<dim3(NPIX / BR, JSPLIT, BATCH), 256, ATTN_SMEM_BYTES>>>();
    merge_kernel<<<dim3(NPIX / 128, BATCH), 256, MERGE_SMEM_BYTES>>>(out);
}